// round 1
// baseline (speedup 1.0000x reference)
#include <cuda_runtime.h>

#define B_    8
#define LQ    4096
#define LK    4096
#define D_    512
#define LSEL  2744
#define SCALE 0.04419417382415922f   // 1/sqrt(512)

// ---------------- scratch (device globals; no allocation allowed) ----------
__device__ float g_kreduce[B_ * D_];
__device__ float g_meanvals[B_ * D_];
__device__ float g_sqk[B_ * LQ];
__device__ float g_thresh[B_];
__device__ int   g_selidx[B_ * LSEL];
__device__ int   g_selcnt[B_];
__device__ float g_S[(size_t)B_ * LSEL * LK];   // ~360 MB score buffer

// ---------------- shared bitonic sort of 4096 floats (ascending) -----------
__device__ __forceinline__ void bitonic4096(float* s) {
    for (int k = 2; k <= 4096; k <<= 1) {
        for (int j = k >> 1; j > 0; j >>= 1) {
            for (int i = threadIdx.x; i < 4096; i += blockDim.x) {
                int ixj = i ^ j;
                if (ixj > i) {
                    float a = s[i], b = s[ixj];
                    if ((a > b) == ((i & k) == 0)) { s[i] = b; s[ixj] = a; }
                }
            }
            __syncthreads();
        }
    }
}

// ---------------- 1. K_reduce: mean of top-LSEL per key column -------------
__global__ void k_kreduce(const float* __restrict__ keys) {
    __shared__ float s[LK];
    __shared__ double red[512];
    int bd = blockIdx.x;            // b*512 + d
    int b = bd >> 9, d = bd & 511;
    const float* kp = keys + (size_t)b * LK * D_ + d;
    for (int i = threadIdx.x; i < LK; i += 512) s[i] = kp[(size_t)i * D_];
    __syncthreads();
    bitonic4096(s);
    double acc = 0.0;
    for (int i = LK - LSEL + threadIdx.x; i < LK; i += 512) acc += (double)s[i];
    red[threadIdx.x] = acc;
    __syncthreads();
    for (int t = 256; t > 0; t >>= 1) {
        if (threadIdx.x < t) red[threadIdx.x] += red[threadIdx.x + t];
        __syncthreads();
    }
    if (threadIdx.x == 0) g_kreduce[bd] = (float)(red[0] / (double)LSEL);
}

// ---------------- 2. mean of values over keys dim ---------------------------
__global__ void k_meanvals(const float* __restrict__ values) {
    int b = blockIdx.x, d = threadIdx.x;
    const float* vp = values + (size_t)b * LK * D_ + d;
    double s = 0.0;
#pragma unroll 8
    for (int k = 0; k < LK; k++) s += (double)vp[(size_t)k * D_];
    g_meanvals[b * D_ + d] = (float)(s / (double)LK);
}

// ---------------- 3. sqk = queries . K_reduce (warp per query) --------------
__global__ void k_sqk(const float* __restrict__ queries) {
    __shared__ float kr[D_];
    int warp = threadIdx.x >> 5, lane = threadIdx.x & 31;
    int qflat = blockIdx.x * 8 + warp;         // 8 queries per block, same batch
    int b = qflat >> 12;
    for (int i = threadIdx.x; i < D_; i += 256) kr[i] = g_kreduce[b * D_ + i];
    __syncthreads();
    const float* qp = queries + (size_t)qflat * D_;
    double acc = 0.0;
#pragma unroll
    for (int j = 0; j < 16; j++) {
        int d = lane + 32 * j;
        acc += (double)qp[d] * (double)kr[d];
    }
    for (int off = 16; off; off >>= 1) acc += __shfl_down_sync(0xffffffffu, acc, off);
    if (lane == 0) g_sqk[qflat] = (float)acc;
}

// ---------------- 4. per-batch selection threshold ---------------------------
__global__ void k_thresh() {
    __shared__ float s[LQ];
    int b = blockIdx.x;
    for (int i = threadIdx.x; i < LQ; i += 512) s[i] = g_sqk[b * LQ + i];
    __syncthreads();
    bitonic4096(s);
    if (threadIdx.x == 0) {
        g_thresh[b] = s[LQ - LSEL];   // 2744th largest
        g_selcnt[b] = 0;
    }
    for (int i = threadIdx.x; i < LSEL; i += 512) g_selidx[b * LSEL + i] = 0;
}

// ---------------- 5. compact selected query indices -------------------------
__global__ void k_compact() {
    int qflat = blockIdx.x * 256 + threadIdx.x;
    int b = qflat >> 12;
    if (g_sqk[qflat] >= g_thresh[b]) {
        int pos = atomicAdd(&g_selcnt[b], 1);
        if (pos < LSEL) g_selidx[b * LSEL + pos] = qflat & 4095;
    }
}

// ---------------- 6. fill unselected rows with mean_values -------------------
__global__ void k_fill(float* __restrict__ out) {
    int r = blockIdx.x;              // b*4096 + q
    int b = r >> 12;
    if (g_sqk[r] < g_thresh[b]) {
        const float4* mv = (const float4*)(g_meanvals + b * D_);
        float4* op = (float4*)(out + (size_t)r * D_);
        op[threadIdx.x] = mv[threadIdx.x];
    }
}

// ---------------- 7. S = scale * Qsel @ K^T  (64x64x16 tiles, 4x4 micro) ----
__global__ void k_gemm_qk(const float* __restrict__ queries,
                          const float* __restrict__ keys) {
    __shared__ float As[16][68];
    __shared__ float Bs[16][68];
    int b = blockIdx.z;
    int m0 = blockIdx.y * 64, n0 = blockIdx.x * 64;
    int tid = threadIdx.x;
    int tx = tid & 15, ty = tid >> 4;
    int lrow = tid >> 2, lc = (tid & 3) * 4;

    int mrow = m0 + lrow;
    int aq = (mrow < LSEL) ? g_selidx[b * LSEL + mrow] : 0;
    const float* ap = queries + ((size_t)b * LQ + aq) * D_;
    const float* bp = keys + ((size_t)b * LK + n0 + lrow) * D_;

    float acc[4][4] = {};
    for (int k0 = 0; k0 < D_; k0 += 16) {
        float4 av = *(const float4*)(ap + k0 + lc);
        float4 bv = *(const float4*)(bp + k0 + lc);
        As[lc + 0][lrow] = av.x; As[lc + 1][lrow] = av.y;
        As[lc + 2][lrow] = av.z; As[lc + 3][lrow] = av.w;
        Bs[lc + 0][lrow] = bv.x; Bs[lc + 1][lrow] = bv.y;
        Bs[lc + 2][lrow] = bv.z; Bs[lc + 3][lrow] = bv.w;
        __syncthreads();
#pragma unroll
        for (int kk = 0; kk < 16; kk++) {
            float a0 = As[kk][ty * 4 + 0], a1 = As[kk][ty * 4 + 1];
            float a2 = As[kk][ty * 4 + 2], a3 = As[kk][ty * 4 + 3];
            float b0 = Bs[kk][tx * 4 + 0], b1 = Bs[kk][tx * 4 + 1];
            float b2 = Bs[kk][tx * 4 + 2], b3 = Bs[kk][tx * 4 + 3];
            acc[0][0] += a0 * b0; acc[0][1] += a0 * b1; acc[0][2] += a0 * b2; acc[0][3] += a0 * b3;
            acc[1][0] += a1 * b0; acc[1][1] += a1 * b1; acc[1][2] += a1 * b2; acc[1][3] += a1 * b3;
            acc[2][0] += a2 * b0; acc[2][1] += a2 * b1; acc[2][2] += a2 * b2; acc[2][3] += a2 * b3;
            acc[3][0] += a3 * b0; acc[3][1] += a3 * b1; acc[3][2] += a3 * b2; acc[3][3] += a3 * b3;
        }
        __syncthreads();
    }
#pragma unroll
    for (int i = 0; i < 4; i++) {
        int row = m0 + ty * 4 + i;
        if (row < LSEL) {
            float* sp = g_S + ((size_t)b * LSEL + row) * LK + n0 + tx * 4;
            sp[0] = acc[i][0] * SCALE; sp[1] = acc[i][1] * SCALE;
            sp[2] = acc[i][2] * SCALE; sp[3] = acc[i][3] * SCALE;
        }
    }
}

// ---------------- 8. row softmax over S (register-resident) -----------------
__global__ void k_softmax() {
    __shared__ float red[256];
    size_t r = blockIdx.x;
    float4* sp4 = (float4*)(g_S + r * LK);
    int tid = threadIdx.x;
    float v[16];
    float mx = -1e30f;
#pragma unroll
    for (int j = 0; j < 4; j++) {
        float4 t = sp4[tid + 256 * j];
        v[4 * j + 0] = t.x; v[4 * j + 1] = t.y; v[4 * j + 2] = t.z; v[4 * j + 3] = t.w;
        mx = fmaxf(mx, fmaxf(fmaxf(t.x, t.y), fmaxf(t.z, t.w)));
    }
    red[tid] = mx; __syncthreads();
    for (int t = 128; t > 0; t >>= 1) {
        if (tid < t) red[tid] = fmaxf(red[tid], red[tid + t]);
        __syncthreads();
    }
    mx = red[0]; __syncthreads();
    float s = 0.f;
#pragma unroll
    for (int i = 0; i < 16; i++) { v[i] = expf(v[i] - mx); s += v[i]; }
    red[tid] = s; __syncthreads();
    for (int t = 128; t > 0; t >>= 1) {
        if (tid < t) red[tid] += red[tid + t];
        __syncthreads();
    }
    float inv = 1.0f / red[0];
#pragma unroll
    for (int j = 0; j < 4; j++) {
        float4 t;
        t.x = v[4 * j + 0] * inv; t.y = v[4 * j + 1] * inv;
        t.z = v[4 * j + 2] * inv; t.w = v[4 * j + 3] * inv;
        sp4[tid + 256 * j] = t;
    }
}

// ---------------- 9. O = P @ V, scatter epilogue -----------------------------
__global__ void k_gemm_pv(const float* __restrict__ values,
                          float* __restrict__ out) {
    __shared__ float As[16][68];
    __shared__ float Bs[16][64];
    int b = blockIdx.z;
    int m0 = blockIdx.y * 64, n0 = blockIdx.x * 64;
    int tid = threadIdx.x;
    int tx = tid & 15, ty = tid >> 4;
    int lrowA = tid >> 2, lcA = (tid & 3) * 4;
    int krow = tid >> 4, nc = (tid & 15) * 4;

    int mrow = m0 + lrowA;
    int mclamp = (mrow < LSEL) ? mrow : (LSEL - 1);
    const float* ap = g_S + ((size_t)b * LSEL + mclamp) * LK;

    float acc[4][4] = {};
    for (int k0 = 0; k0 < LK; k0 += 16) {
        float4 av = *(const float4*)(ap + k0 + lcA);
        As[lcA + 0][lrowA] = av.x; As[lcA + 1][lrowA] = av.y;
        As[lcA + 2][lrowA] = av.z; As[lcA + 3][lrowA] = av.w;
        float4 bv = *(const float4*)(values + ((size_t)b * LK + k0 + krow) * D_ + n0 + nc);
        *(float4*)&Bs[krow][nc] = bv;
        __syncthreads();
#pragma unroll
        for (int kk = 0; kk < 16; kk++) {
            float a0 = As[kk][ty * 4 + 0], a1 = As[kk][ty * 4 + 1];
            float a2 = As[kk][ty * 4 + 2], a3 = As[kk][ty * 4 + 3];
            float b0 = Bs[kk][tx * 4 + 0], b1 = Bs[kk][tx * 4 + 1];
            float b2 = Bs[kk][tx * 4 + 2], b3 = Bs[kk][tx * 4 + 3];
            acc[0][0] += a0 * b0; acc[0][1] += a0 * b1; acc[0][2] += a0 * b2; acc[0][3] += a0 * b3;
            acc[1][0] += a1 * b0; acc[1][1] += a1 * b1; acc[1][2] += a1 * b2; acc[1][3] += a1 * b3;
            acc[2][0] += a2 * b0; acc[2][1] += a2 * b1; acc[2][2] += a2 * b2; acc[2][3] += a2 * b3;
            acc[3][0] += a3 * b0; acc[3][1] += a3 * b1; acc[3][2] += a3 * b2; acc[3][3] += a3 * b3;
        }
        __syncthreads();
    }
#pragma unroll
    for (int i = 0; i < 4; i++) {
        int row = m0 + ty * 4 + i;
        if (row < LSEL) {
            int q = g_selidx[b * LSEL + row];
            float* op = out + ((size_t)b * LQ + q) * D_ + n0 + tx * 4;
            op[0] = acc[i][0]; op[1] = acc[i][1];
            op[2] = acc[i][2]; op[3] = acc[i][3];
        }
    }
}

// ---------------- launch ------------------------------------------------------
extern "C" void kernel_launch(void* const* d_in, const int* in_sizes, int n_in,
                              void* d_out, int out_size) {
    const float* q = (const float*)d_in[0];
    const float* k = (const float*)d_in[1];
    const float* v = (const float*)d_in[2];
    float* out = (float*)d_out;

    k_kreduce<<<B_ * D_, 512>>>(k);
    k_meanvals<<<B_, 512>>>(v);
    k_sqk<<<B_ * LQ / 8, 256>>>(q);
    k_thresh<<<B_, 512>>>();
    k_compact<<<B_ * LQ / 256, 256>>>();
    k_fill<<<B_ * LQ, 128>>>(out);

    dim3 g1(LK / 64, (LSEL + 63) / 64, B_);
    k_gemm_qk<<<g1, 256>>>(q, k);

    k_softmax<<<B_ * LSEL, 256>>>();

    dim3 g2(D_ / 64, (LSEL + 63) / 64, B_);
    k_gemm_pv<<<g2, 256>>>(v, out);
}